// round 1
// baseline (speedup 1.0000x reference)
#include <cuda_runtime.h>
#include <cstddef>

// Index map for pred_raw[b, 4h+i, 4w+j] = y[b, C[k], 4h+RO[k], 4w+CO[k]], k = 4*i+j.
// Derived from: stack order (rr,gr,gb,bb) composed with _PERM = [0,1,4,5,2,3,6,7,8,9,12,13,10,11,14,5].
__constant__ int kC[16]  = {0, 3, 1, 4,   6, 9, 7, 10,   1, 4, 8, 10,   2, 5, 9, 4};
__constant__ int kRO[16] = {0, 0, 0, 0,   1, 1, 1, 1,    2, 2, 3, 3,    2, 2, 3, 0};
__constant__ int kCO[16] = {0, 1, 2, 3,   0, 1, 2, 3,    0, 1, 0, 1,    2, 3, 2, 3};

#define NQUADS   (8 * 1024 * 256)      // one thread per 4-pixel quad
#define NBLOCKS  (NQUADS / 256)        // 8192
#define N_TOTAL  8388608.0f            // 8*1024*1024 output pixels

__device__ float g_partials[NBLOCKS];

__global__ void __launch_bounds__(256)
loss_main(const float* __restrict__ x, const float* __restrict__ y) {
    const int t  = blockIdx.x * 256 + threadIdx.x;   // [0, 2^21)
    const int wq = t & 255;            // quad column  (cols 4wq..4wq+3)
    const int H  = (t >> 8) & 1023;    // output row
    const int b  = t >> 18;            // batch
    const int i  = H & 3;
    const int h  = H >> 2;

    // x: fully coalesced 16B/thread
    const float4 xv = *reinterpret_cast<const float4*>(
        x + ((((size_t)b << 10) + H) << 10) + ((size_t)wq << 2));
    const float xs0 = xv.x, xs1 = xv.y, xs2 = xv.z, xs3 = xv.w;

    const int kb = i << 2;
    float s = 0.0f;
    // 4 independent scalar y loads (MLP=4); stride 16B across the warp touches
    // exactly the sectors that must be fetched (no amplification beyond floor).
    {
        int k = kb + 0;
        size_t off = ((((size_t)(b * 12 + kC[k]) << 10) + (h << 2) + kRO[k]) << 10)
                     + (wq << 2) + kCO[k];
        s += fabsf(y[off] - xs0);
    }
    {
        int k = kb + 1;
        size_t off = ((((size_t)(b * 12 + kC[k]) << 10) + (h << 2) + kRO[k]) << 10)
                     + (wq << 2) + kCO[k];
        s += fabsf(y[off] - xs1);
    }
    {
        int k = kb + 2;
        size_t off = ((((size_t)(b * 12 + kC[k]) << 10) + (h << 2) + kRO[k]) << 10)
                     + (wq << 2) + kCO[k];
        s += fabsf(y[off] - xs2);
    }
    {
        int k = kb + 3;
        size_t off = ((((size_t)(b * 12 + kC[k]) << 10) + (h << 2) + kRO[k]) << 10)
                     + (wq << 2) + kCO[k];
        s += fabsf(y[off] - xs3);
    }

    // Deterministic block reduction
    #pragma unroll
    for (int m = 16; m > 0; m >>= 1)
        s += __shfl_xor_sync(0xFFFFFFFFu, s, m);

    __shared__ float sm[8];
    const int lane = threadIdx.x & 31;
    const int warp = threadIdx.x >> 5;
    if (lane == 0) sm[warp] = s;
    __syncthreads();
    if (warp == 0) {
        float v = (lane < 8) ? sm[lane] : 0.0f;
        #pragma unroll
        for (int m = 4; m > 0; m >>= 1)
            v += __shfl_xor_sync(0xFFFFFFFFu, v, m);
        if (lane == 0) g_partials[blockIdx.x] = v;
    }
}

__global__ void __launch_bounds__(256)
loss_reduce(float* __restrict__ out) {
    float s = 0.0f;
    for (int idx = threadIdx.x; idx < NBLOCKS; idx += 256)
        s += g_partials[idx];

    #pragma unroll
    for (int m = 16; m > 0; m >>= 1)
        s += __shfl_xor_sync(0xFFFFFFFFu, s, m);

    __shared__ float sm[8];
    const int lane = threadIdx.x & 31;
    const int warp = threadIdx.x >> 5;
    if (lane == 0) sm[warp] = s;
    __syncthreads();
    if (warp == 0) {
        float v = (lane < 8) ? sm[lane] : 0.0f;
        #pragma unroll
        for (int m = 4; m > 0; m >>= 1)
            v += __shfl_xor_sync(0xFFFFFFFFu, v, m);
        if (lane == 0) out[0] = v * (1.0f / N_TOTAL);
    }
}

extern "C" void kernel_launch(void* const* d_in, const int* in_sizes, int n_in,
                              void* d_out, int out_size) {
    // x is 8*1024*1024 elems, y is 8*12*1024*1024 — detect order defensively.
    const float* x;
    const float* y;
    if (in_sizes[0] == 8 * 1024 * 1024) {
        x = (const float*)d_in[0];
        y = (const float*)d_in[1];
    } else {
        x = (const float*)d_in[1];
        y = (const float*)d_in[0];
    }
    float* out = (float*)d_out;

    loss_main<<<NBLOCKS, 256>>>(x, y);
    loss_reduce<<<1, 256>>>(out);
}

// round 2
// speedup vs baseline: 1.0597x; 1.0597x over previous
#include <cuda_runtime.h>
#include <cstddef>

// pred_raw[b, 4h+i, 4w+j] = y[b, C[k], 4h+RO[k], 4w+CO[k]], k = 4*i+j.
// k=15 duplicates k=3 exactly (from _PERM[15]=5) -> reuse in-register.

#define NB 2048                  // 8 batches * 256 h-tiles
#define N_TOTAL 8388608.0f

__device__ float g_partials[NB];
__device__ unsigned int g_count = 0;

__global__ void __launch_bounds__(256)
loss_fused(const float* __restrict__ x, const float* __restrict__ y,
           float* __restrict__ out)
{
    const int g  = blockIdx.x;
    const int wq = threadIdx.x;          // tile column: output cols 4wq..4wq+3
    const int b  = g >> 8;               // batch
    const int h  = g & 255;              // tile row: output rows 4h..4h+3

    const int kC[16]  = {0,3,1,4, 6,9,7,10, 1,4,8,10, 2,5,9,4};
    const int kRO[16] = {0,0,0,0, 1,1,1,1,  2,2,3,3,  2,2,3,0};
    const int kCO[16] = {0,1,2,3, 0,1,2,3,  0,1,0,1,  2,3,2,3};

    // x: 4 coalesced float4 rows of the 4x4 tile
    float xs[16];
    {
        const size_t xbase = ((((size_t)b << 10) + (h << 2)) << 10) + (wq << 2);
        #pragma unroll
        for (int i = 0; i < 4; i++) {
            float4 v = *reinterpret_cast<const float4*>(x + xbase + ((size_t)i << 10));
            xs[4*i+0] = v.x; xs[4*i+1] = v.y; xs[4*i+2] = v.z; xs[4*i+3] = v.w;
        }
    }

    // y: 15 unique scalar loads (k=15 reuses k=3). All independent -> MLP=19.
    float yv[16];
    #pragma unroll
    for (int k = 0; k < 15; k++) {
        size_t off = ((((size_t)(b * 12 + kC[k]) << 10) + (h << 2) + kRO[k]) << 10)
                     + (wq << 2) + kCO[k];
        yv[k] = y[off];
    }
    yv[15] = yv[3];

    float s = 0.0f;
    #pragma unroll
    for (int k = 0; k < 16; k++)
        s += fabsf(yv[k] - xs[k]);

    // ---- deterministic block reduction ----
    #pragma unroll
    for (int m = 16; m > 0; m >>= 1)
        s += __shfl_xor_sync(0xFFFFFFFFu, s, m);

    __shared__ float sm[8];
    __shared__ bool  is_last;
    const int lane = threadIdx.x & 31;
    const int warp = threadIdx.x >> 5;
    if (lane == 0) sm[warp] = s;
    __syncthreads();

    if (threadIdx.x == 0) {
        float v = 0.0f;
        #pragma unroll
        for (int w = 0; w < 8; w++) v += sm[w];
        g_partials[g] = v;
        __threadfence();
        unsigned int prev = atomicAdd(&g_count, 1u);
        is_last = (prev == NB - 1);
    }
    __syncthreads();

    // ---- last block performs the final (deterministic, fixed-order) sum ----
    if (is_last) {
        float t = 0.0f;
        #pragma unroll 8
        for (int idx = threadIdx.x; idx < NB; idx += 256)
            t += g_partials[idx];
        #pragma unroll
        for (int m = 16; m > 0; m >>= 1)
            t += __shfl_xor_sync(0xFFFFFFFFu, t, m);
        if (lane == 0) sm[warp] = t;
        __syncthreads();
        if (threadIdx.x == 0) {
            float v = 0.0f;
            #pragma unroll
            for (int w = 0; w < 8; w++) v += sm[w];
            out[0] = v * (1.0f / N_TOTAL);
            g_count = 0;     // reset for next graph replay
        }
    }
}

extern "C" void kernel_launch(void* const* d_in, const int* in_sizes, int n_in,
                              void* d_out, int out_size) {
    const float* x;
    const float* y;
    if (in_sizes[0] == 8 * 1024 * 1024) {
        x = (const float*)d_in[0];
        y = (const float*)d_in[1];
    } else {
        x = (const float*)d_in[1];
        y = (const float*)d_in[0];
    }
    loss_fused<<<NB, 256>>>(x, y, (float*)d_out);
}